// round 2
// baseline (speedup 1.0000x reference)
#include <cuda_runtime.h>
#include <math.h>

// Deterministic two-pass reduction for:
//   l_i = where(isfinite(d[:,0]-d[:,1]), d[:,0]-d[:,1], 0)
//   t01 = 1 - max(l0)^2 ; t0 = sum(l0^2) - max(l0)^2 ; t1 = sum(l1^2) ; t2 = sum(l2^2)
//   loss = t01 + t0 + t1 + t2
// Output: 5 floats [loss, t01, t0, t1, t2]

#define NBLK 1024
#define NTHR 256

__device__ double g_s0[NBLK];
__device__ double g_s1[NBLK];
__device__ double g_s2[NBLK];
__device__ float  g_m0[NBLK];

__device__ __forceinline__ float fin_len(float a, float b) {
    float l = a - b;
    return isfinite(l) ? l : 0.0f;
}

__device__ __forceinline__ void acc4(float4 v, double& s) {
    float l0 = fin_len(v.x, v.y);
    float l1 = fin_len(v.z, v.w);
    s += (double)l0 * (double)l0 + (double)l1 * (double)l1;
}

__device__ __forceinline__ void acc4m(float4 v, double& s, float& m) {
    float l0 = fin_len(v.x, v.y);
    float l1 = fin_len(v.z, v.w);
    s += (double)l0 * (double)l0 + (double)l1 * (double)l1;
    m = fmaxf(m, fmaxf(l0, l1));
}

__global__ __launch_bounds__(NTHR) void pass1(
    const float4* __restrict__ d0,
    const float4* __restrict__ d1,
    const float4* __restrict__ d2,
    int n4)
{
    double s0 = 0.0, s1 = 0.0, s2 = 0.0;
    float m0 = -__int_as_float(0x7f800000);  // -inf

    const int stride  = gridDim.x * blockDim.x;   // 256K threads
    const int stride2 = stride * 2;

    int i = blockIdx.x * blockDim.x + threadIdx.x;
    // Unrolled x2: front-batch 6 independent LDG.128 per iteration for MLP.
    for (; i + stride < n4; i += stride2) {
        float4 a0 = d0[i];
        float4 a1 = d0[i + stride];
        float4 b0 = d1[i];
        float4 b1 = d1[i + stride];
        float4 c0 = d2[i];
        float4 c1 = d2[i + stride];

        acc4m(a0, s0, m0);
        acc4m(a1, s0, m0);
        acc4(b0, s1);
        acc4(b1, s1);
        acc4(c0, s2);
        acc4(c1, s2);
    }
    if (i < n4) {
        float4 a0 = d0[i];
        float4 b0 = d1[i];
        float4 c0 = d2[i];
        acc4m(a0, s0, m0);
        acc4(b0, s1);
        acc4(c0, s2);
    }

    __shared__ double sh0[NTHR];
    __shared__ double sh1[NTHR];
    __shared__ double sh2[NTHR];
    __shared__ float  shm[NTHR];

    int t = threadIdx.x;
    sh0[t] = s0; sh1[t] = s1; sh2[t] = s2; shm[t] = m0;
    __syncthreads();

    for (int off = NTHR / 2; off > 0; off >>= 1) {
        if (t < off) {
            sh0[t] += sh0[t + off];
            sh1[t] += sh1[t + off];
            sh2[t] += sh2[t + off];
            shm[t] = fmaxf(shm[t], shm[t + off]);
        }
        __syncthreads();
    }

    if (t == 0) {
        g_s0[blockIdx.x] = sh0[0];
        g_s1[blockIdx.x] = sh1[0];
        g_s2[blockIdx.x] = sh2[0];
        g_m0[blockIdx.x] = shm[0];
    }
}

__global__ __launch_bounds__(NTHR) void pass2(float* __restrict__ out)
{
    double s0 = 0.0, s1 = 0.0, s2 = 0.0;
    float m0 = -__int_as_float(0x7f800000);

    int t = threadIdx.x;
    #pragma unroll
    for (int i = t; i < NBLK; i += NTHR) {
        s0 += g_s0[i];
        s1 += g_s1[i];
        s2 += g_s2[i];
        m0 = fmaxf(m0, g_m0[i]);
    }

    __shared__ double sh0[NTHR];
    __shared__ double sh1[NTHR];
    __shared__ double sh2[NTHR];
    __shared__ float  shm[NTHR];

    sh0[t] = s0; sh1[t] = s1; sh2[t] = s2; shm[t] = m0;
    __syncthreads();

    for (int off = NTHR / 2; off > 0; off >>= 1) {
        if (t < off) {
            sh0[t] += sh0[t + off];
            sh1[t] += sh1[t + off];
            sh2[t] += sh2[t + off];
            shm[t] = fmaxf(shm[t], shm[t + off]);
        }
        __syncthreads();
    }

    if (t == 0) {
        double top1  = (double)shm[0];
        double top1s = top1 * top1;
        double t01 = 1.0 - top1s;
        double t0  = sh0[0] - top1s;
        double t1  = sh1[0];
        double t2  = sh2[0];
        double loss = t01 + t0 + t1 + t2;
        out[0] = (float)loss;
        out[1] = (float)t01;
        out[2] = (float)t0;
        out[3] = (float)t1;
        out[4] = (float)t2;
    }
}

extern "C" void kernel_launch(void* const* d_in, const int* in_sizes, int n_in,
                              void* d_out, int out_size)
{
    const float4* d0 = (const float4*)d_in[0];
    const float4* d1 = (const float4*)d_in[1];
    const float4* d2 = (const float4*)d_in[2];
    float* out = (float*)d_out;

    int n4 = in_sizes[0] / 4;  // floats -> float4 (2 bars each)

    pass1<<<NBLK, NTHR>>>(d0, d1, d2, n4);
    pass2<<<1, NTHR>>>(out);
}

// round 3
// speedup vs baseline: 1.0546x; 1.0546x over previous
#include <cuda_runtime.h>
#include <math.h>

// Single-kernel deterministic reduction (last-block-done pattern) for:
//   l_i = where(isfinite(d[:,0]-d[:,1]), d[:,0]-d[:,1], 0)
//   t01 = 1 - max(l0)^2 ; t0 = sum(l0^2) - max(l0)^2 ; t1 = sum(l1^2) ; t2 = sum(l2^2)
//   loss = t01 + t0 + t1 + t2
// Output: 5 floats [loss, t01, t0, t1, t2]

#define NBLK 1024
#define NTHR 256
#define NWARP (NTHR / 32)

__device__ double g_s0[NBLK];
__device__ double g_s1[NBLK];
__device__ double g_s2[NBLK];
__device__ float  g_m0[NBLK];
__device__ unsigned int g_count;   // zero-initialized; reset to 0 by last block each run

__device__ __forceinline__ float fin_len(float a, float b) {
    float l = a - b;
    return isfinite(l) ? l : 0.0f;
}

__device__ __forceinline__ void acc4(float4 v, float& s) {
    float l0 = fin_len(v.x, v.y);
    float l1 = fin_len(v.z, v.w);
    s = fmaf(l0, l0, s);
    s = fmaf(l1, l1, s);
}

__device__ __forceinline__ void acc4m(float4 v, float& s, float& m) {
    float l0 = fin_len(v.x, v.y);
    float l1 = fin_len(v.z, v.w);
    s = fmaf(l0, l0, s);
    s = fmaf(l1, l1, s);
    m = fmaxf(m, fmaxf(l0, l1));
}

__global__ __launch_bounds__(NTHR) void toploss_kernel(
    const float4* __restrict__ d0,
    const float4* __restrict__ d1,
    const float4* __restrict__ d2,
    float* __restrict__ out,
    int n4)
{
    float s0 = 0.0f, s1 = 0.0f, s2 = 0.0f;
    float m0 = -__int_as_float(0x7f800000);  // -inf

    const int stride  = gridDim.x * blockDim.x;   // 262144 threads
    const int stride4 = stride * 4;

    int i = blockIdx.x * blockDim.x + threadIdx.x;
    // Unroll x4: front-batch 12 independent LDG.128 per iteration for MLP.
    for (; i + 3 * stride < n4; i += stride4) {
        float4 a0 = d0[i];
        float4 a1 = d0[i + stride];
        float4 a2 = d0[i + 2 * stride];
        float4 a3 = d0[i + 3 * stride];
        float4 b0 = d1[i];
        float4 b1 = d1[i + stride];
        float4 b2 = d1[i + 2 * stride];
        float4 b3 = d1[i + 3 * stride];
        float4 c0 = d2[i];
        float4 c1 = d2[i + stride];
        float4 c2 = d2[i + 2 * stride];
        float4 c3 = d2[i + 3 * stride];

        acc4m(a0, s0, m0); acc4m(a1, s0, m0); acc4m(a2, s0, m0); acc4m(a3, s0, m0);
        acc4(b0, s1); acc4(b1, s1); acc4(b2, s1); acc4(b3, s1);
        acc4(c0, s2); acc4(c1, s2); acc4(c2, s2); acc4(c3, s2);
    }
    for (; i < n4; i += stride) {
        float4 a0 = d0[i];
        float4 b0 = d1[i];
        float4 c0 = d2[i];
        acc4m(a0, s0, m0);
        acc4(b0, s1);
        acc4(c0, s2);
    }

    // ---- block reduce: warp shuffles then cross-warp via smem ----
    double ds0 = (double)s0, ds1 = (double)s1, ds2 = (double)s2;
    #pragma unroll
    for (int off = 16; off > 0; off >>= 1) {
        ds0 += __shfl_down_sync(0xffffffffu, ds0, off);
        ds1 += __shfl_down_sync(0xffffffffu, ds1, off);
        ds2 += __shfl_down_sync(0xffffffffu, ds2, off);
        m0   = fmaxf(m0, __shfl_down_sync(0xffffffffu, m0, off));
    }

    __shared__ double sh0[NWARP];
    __shared__ double sh1[NWARP];
    __shared__ double sh2[NWARP];
    __shared__ float  shm[NWARP];

    int lane = threadIdx.x & 31;
    int warp = threadIdx.x >> 5;
    if (lane == 0) {
        sh0[warp] = ds0; sh1[warp] = ds1; sh2[warp] = ds2; shm[warp] = m0;
    }
    __syncthreads();

    if (warp == 0) {
        double t0v = (lane < NWARP) ? sh0[lane] : 0.0;
        double t1v = (lane < NWARP) ? sh1[lane] : 0.0;
        double t2v = (lane < NWARP) ? sh2[lane] : 0.0;
        float  tmv = (lane < NWARP) ? shm[lane] : -__int_as_float(0x7f800000);
        #pragma unroll
        for (int off = 16; off > 0; off >>= 1) {
            t0v += __shfl_down_sync(0xffffffffu, t0v, off);
            t1v += __shfl_down_sync(0xffffffffu, t1v, off);
            t2v += __shfl_down_sync(0xffffffffu, t2v, off);
            tmv  = fmaxf(tmv, __shfl_down_sync(0xffffffffu, tmv, off));
        }
        if (lane == 0) {
            g_s0[blockIdx.x] = t0v;
            g_s1[blockIdx.x] = t1v;
            g_s2[blockIdx.x] = t2v;
            g_m0[blockIdx.x] = tmv;
        }
    }

    // ---- last-block-done: final reduce over NBLK partials ----
    __shared__ bool is_last;
    __threadfence();
    __syncthreads();
    if (threadIdx.x == 0) {
        unsigned int prev = atomicAdd(&g_count, 1u);
        is_last = (prev == (unsigned int)(gridDim.x - 1));
    }
    __syncthreads();
    if (!is_last) return;

    double f0 = 0.0, f1 = 0.0, f2 = 0.0;
    float  fm = -__int_as_float(0x7f800000);
    for (int k = threadIdx.x; k < NBLK; k += NTHR) {
        f0 += g_s0[k];
        f1 += g_s1[k];
        f2 += g_s2[k];
        fm  = fmaxf(fm, g_m0[k]);
    }
    #pragma unroll
    for (int off = 16; off > 0; off >>= 1) {
        f0 += __shfl_down_sync(0xffffffffu, f0, off);
        f1 += __shfl_down_sync(0xffffffffu, f1, off);
        f2 += __shfl_down_sync(0xffffffffu, f2, off);
        fm  = fmaxf(fm, __shfl_down_sync(0xffffffffu, fm, off));
    }

    __shared__ double fs0[NWARP];
    __shared__ double fs1[NWARP];
    __shared__ double fs2[NWARP];
    __shared__ float  fsm[NWARP];
    if (lane == 0) {
        fs0[warp] = f0; fs1[warp] = f1; fs2[warp] = f2; fsm[warp] = fm;
    }
    __syncthreads();

    if (threadIdx.x == 0) {
        double a0 = 0.0, a1 = 0.0, a2 = 0.0;
        float  am = -__int_as_float(0x7f800000);
        #pragma unroll
        for (int w = 0; w < NWARP; w++) {
            a0 += fs0[w]; a1 += fs1[w]; a2 += fs2[w];
            am  = fmaxf(am, fsm[w]);
        }
        double top1  = (double)am;
        double top1s = top1 * top1;
        double t01 = 1.0 - top1s;
        double t0  = a0 - top1s;
        double loss = t01 + t0 + a1 + a2;
        out[0] = (float)loss;
        out[1] = (float)t01;
        out[2] = (float)t0;
        out[3] = (float)a1;
        out[4] = (float)a2;
        g_count = 0;   // reset for next graph replay (deterministic)
    }
}

extern "C" void kernel_launch(void* const* d_in, const int* in_sizes, int n_in,
                              void* d_out, int out_size)
{
    const float4* d0 = (const float4*)d_in[0];
    const float4* d1 = (const float4*)d_in[1];
    const float4* d2 = (const float4*)d_in[2];
    float* out = (float*)d_out;

    int n4 = in_sizes[0] / 4;  // floats -> float4 (2 bars each)

    toploss_kernel<<<NBLK, NTHR>>>(d0, d1, d2, out, n4);
}